// round 6
// baseline (speedup 1.0000x reference)
#include <cuda_runtime.h>

// Problem shape (fixed by setup_inputs): B=4, L=4096, D=1024
#define BB 4
#define LL 4096
#define DD 1024
#define TT 32               // timesteps per chunk
#define CMAX (LL / TT)      // 128 max chunks (Nb <= L)

// ---------------- scratch (no allocations allowed) ----------------
__device__ int   g_mode;                    // 0: u8 mask, 1: int32 mask, 2: f32 mask
__device__ int   g_nb[BB];                  // boundary count per batch
__device__ int   g_bidx[BB][LL + 1];        // boundary positions + sentinel L
__device__ float g_p[BB][LL];               // clipped boundary probs (sorted order)
__device__ float g_A[BB][CMAX];             // per-chunk decay product (scalar)
__device__ float g_U[BB][CMAX][DD];         // per-chunk local scan end state
__device__ float g_Hin[BB][CMAX][DD];       // carry-in state per chunk

// ---------------- kernel 0: detect mask dtype --------------------
// numpy bool (u8 0/1): nonzero bytes can occur at any offset mod 4 (incl. 1).
// int32 0/1 LE: nonzero bytes only at offset%4==0.
// f32 0.0/1.0:  nonzero bytes only at offset%4 in {2,3} (0x80, 0x3F).
// With ~25% true over 16384 elements, offset%4==1 nonzero occurs w.p. ~1 for u8.
__global__ void k_detect(const unsigned char* __restrict__ m) {
    __shared__ int f1, f0;
    if (threadIdx.x == 0) { f1 = 0; f0 = 0; }
    __syncthreads();
    int a1 = 0, a0 = 0;
    for (int i = threadIdx.x; i < BB * LL; i += blockDim.x) {
        unsigned char v = m[i];
        if (v) {
            int r = i & 3;
            if (r == 1) a1 = 1;
            else if (r == 0) a0 = 1;
        }
    }
    if (a1) atomicOr(&f1, 1);
    if (a0) atomicOr(&f0, 1);
    __syncthreads();
    if (threadIdx.x == 0) g_mode = f1 ? 0 : (f0 ? 1 : 2);
}

__device__ __forceinline__ int mask_at(const unsigned char* m, int mode, int idx) {
    if (mode == 0) return m[idx] != 0;
    if (mode == 1) return ((const int*)m)[idx] != 0;
    return ((const float*)m)[idx] != 0.0f;
}

// ---------------- kernel 1: per-batch setup ----------------------
// Block per batch (1024 threads, 4 elems each): block-wide inclusive scan of
// the mask -> boundary indices, clipped p in sorted order, chunk scalars A_c.
__global__ void k_setup(const unsigned char* __restrict__ mask,
                        const float* __restrict__ prob) {
    int b = blockIdx.x, tid = threadIdx.x;
    int mode = g_mode;
    int base = tid * 4;

    int mv[4]; int s = 0;
#pragma unroll
    for (int k = 0; k < 4; k++) { mv[k] = mask_at(mask, mode, b * LL + base + k); s += mv[k]; }

    int lane = tid & 31, wp = tid >> 5;
    int v = s;
#pragma unroll
    for (int o = 1; o < 32; o <<= 1) {
        int n = __shfl_up_sync(0xffffffffu, v, o);
        if (lane >= o) v += n;
    }
    __shared__ int wsum[32];
    if (lane == 31) wsum[wp] = v;
    __syncthreads();
    if (wp == 0) {
        int w = wsum[lane];
#pragma unroll
        for (int o = 1; o < 32; o <<= 1) {
            int n = __shfl_up_sync(0xffffffffu, w, o);
            if (lane >= o) w += n;
        }
        wsum[lane] = w;
    }
    __syncthreads();
    int excl = v - s + (wp ? wsum[wp - 1] : 0);

    int j = excl;
#pragma unroll
    for (int k = 0; k < 4; k++) {
        if (mv[k]) {
            g_bidx[b][j] = base + k;
            float pv = prob[((size_t)(b * LL + base + k)) * 2 + 1];
            pv = fminf(fmaxf(pv, 1e-4f), 1.0f - 1e-4f);
            g_p[b][j] = pv;
            j++;
        }
    }
    int Nb = wsum[31];
    if (tid == 0) { g_nb[b] = Nb; g_bidx[b][Nb] = LL; }
    __syncthreads();   // g_p fully written (block-scope fence covers global)

    int C = (Nb + TT - 1) / TT;
    for (int c = tid; c < C; c += blockDim.x) {
        float a = 1.0f;
        int j0 = c * TT, j1 = min(j0 + TT, Nb);
        for (int jj = j0; jj < j1; jj++) a *= (1.0f - g_p[b][jj]);
        g_A[b][c] = a;
    }
}

// ---------------- kernel 2: chunk-local partial scans ------------
// One block per (chunk, batch), one thread per channel. Zero-init local scan,
// store end state U. Coalesced streaming reads of hidden_states.
__global__ void __launch_bounds__(DD, 2)
k_partial(const float* __restrict__ hs) {
    int c = blockIdx.x, b = blockIdx.y, d = threadIdx.x;
    int Nb = g_nb[b];
    int j0 = c * TT;
    if (j0 >= Nb) return;
    int n = min(TT, Nb - j0);

    __shared__ float sp[TT];
    if (d < n) sp[d] = g_p[b][j0 + d];
    __syncthreads();

    const float* xb = hs + ((size_t)b * LL + j0) * DD + d;
    float g = 0.0f;
    for (int t = 0; t < n; t++) {
        float p = sp[t];
        g = (1.0f - p) * g + p * xb[(size_t)t * DD];
    }
    g_U[b][c][d] = g;
}

// ---------------- kernel 3: carry combine across chunks ----------
// Hin[c] = state entering chunk c.  s_{c+1} = A_c * s_c + U_c.
__global__ void k_carry() {
    int b = blockIdx.x, d = threadIdx.x;
    int Nb = g_nb[b];
    int C = (Nb + TT - 1) / TT;
    float s = 0.0f;
    for (int c = 0; c < C; c++) {
        g_Hin[b][c][d] = s;
        s = g_A[b][c] * s + g_U[b][c][d];
    }
}

// ---------------- kernel 4: finalize + run-scatter ---------------
// Redo the chunk scan with the true carry-in and write h_j directly to the
// output rows of its segment [bidx[j], bidx[j+1]). Covers all L rows since
// bidx[0]==0 (first token forced boundary).
__global__ void __launch_bounds__(DD, 2)
k_final(const float* __restrict__ hs, float* __restrict__ out) {
    int c = blockIdx.x, b = blockIdx.y, d = threadIdx.x;
    int Nb = g_nb[b];
    int j0 = c * TT;
    if (j0 >= Nb) return;
    int n = min(TT, Nb - j0);

    __shared__ float sp[TT];
    __shared__ int   sb[TT + 1];
    if (d < n)  sp[d] = g_p[b][j0 + d];
    if (d <= n) sb[d] = g_bidx[b][j0 + d];   // sb[n] = next boundary or L
    __syncthreads();

    const float* xb = hs + ((size_t)b * LL + j0) * DD + d;
    float* ob = out + (size_t)b * LL * DD + d;

    float h = g_Hin[b][c][d];
    for (int t = 0; t < n; t++) {
        float p = sp[t];
        h = (1.0f - p) * h + p * xb[(size_t)t * DD];
        int l0 = sb[t], l1 = sb[t + 1];
        for (int l = l0; l < l1; l++) ob[(size_t)l * DD] = h;
    }
}

// ---------------- launch -----------------------------------------
extern "C" void kernel_launch(void* const* d_in, const int* in_sizes, int n_in,
                              void* d_out, int out_size) {
    (void)in_sizes; (void)n_in; (void)out_size;
    const float*         hs   = (const float*)d_in[0];
    const float*         prob = (const float*)d_in[1];
    const unsigned char* mask = (const unsigned char*)d_in[2];
    float*               out  = (float*)d_out;

    k_detect <<<1, 1024>>>(mask);
    k_setup  <<<BB, 1024>>>(mask, prob);
    k_partial<<<dim3(CMAX, BB), DD>>>(hs);
    k_carry  <<<BB, DD>>>();
    k_final  <<<dim3(CMAX, BB), DD>>>(hs, out);
}